// round 9
// baseline (speedup 1.0000x reference)
#include <cuda_runtime.h>

// ISTSimulator: B=65536, V=2, L=200 per-lane recurrence.
// Round 9: geometric sigmoid with 8-step exact reseed + warp-uniform hazard
// votes. Cheap path: 3.125 MUFU/step (lg2, ex2(pow), rcp + reseed/8).
// Expensive path (steep lanes / pinned-crossing groups): R8's exact 4-MUFU path.
// 128-thread blocks, 32-step smem staging + coalesced float4 flush.

#define LOG2E_F 1.4426950408889634f
#define SW 33                          // smem row stride (odd -> conflict-free)
#define BT 128                         // threads per block

__device__ __forceinline__ float ex2a(float x) {
    float r; asm("ex2.approx.ftz.f32 %0, %1;" : "=f"(r) : "f"(x)); return r;
}
__device__ __forceinline__ float lg2a(float x) {
    float r; asm("lg2.approx.f32 %0, %1;" : "=f"(r) : "f"(x)); return r;
}
__device__ __forceinline__ float rcpa(float x) {
    float r; asm("rcp.approx.ftz.f32 %0, %1;" : "=f"(r) : "f"(x)); return r;
}

__global__ void __launch_bounds__(BT) ist_staged_kernel(
    const float* __restrict__ in, float* __restrict__ out)
{
    __shared__ float sm[BT * SW];      // 16.9 KB
    int t = threadIdx.x;
    int base_lane = blockIdx.x * BT;
    int lane = base_lane + t;

    const float* p = in + (size_t)lane * 7;
    float lam  = 0.001f * fmaxf(p[0], 0.0f);
    float nlam = -lam;
    float beta = fmaf(10.0f, fmaxf(p[1], 0.0f), 1.0f);
    float kd   = p[2];
    float mu   = p[3];
    float kf   = p[4];
    float a    = LOG2E_F / p[6];       // sigmoid: g = 1/(1 + 2^((nc-n)*a))
    float z0   = p[5] * a;
    float na   = -a;
    float nkd  = -kd;
    float c    = ex2a(na);             // geometric ratio 2^{-a}

    // Warp-uniform gate: geometric path only if every lane's c is a normal,
    // finite, nonzero float (|a| < 126). Also excludes NaN a (wt==0 pathology).
    bool warp_geo = __all_sync(0xffffffffu, fabsf(a) < 126.0f);

    float u  = 1.0f;                   // u = 1 - D; stays in (0.3, 1]
    float F  = 1e-12f;
    float* sp = &sm[t * SW];

    #pragma unroll 1
    for (int chunk = 0; chunk < 6; ++chunk) {
        int n0 = chunk * 32;
        #pragma unroll
        for (int j8 = 0; j8 < 32; j8 += 8) {
            float zs = fmaf((float)(n0 + j8), na, z0);   // exact group-start z
            float ze = fmaf(8.0f, na, zs);               // group-end z
            // Hazard: e pinned at reseed (inf / FTZ-0) while true g crosses
            // back toward 0.5 within the group. z monotone -> this predicate
            // is exact. Benign saturated groups stay cheap (g==0/1 to 2^-26).
            bool pin_cross = (zs >  126.0f && ze <  26.0f) ||
                             (zs < -126.0f && ze > -26.0f);
            bool cheap = warp_geo && !__any_sync(0xffffffffu, pin_cross);

            if (cheap) {
                float e = ex2a(zs);                      // exact reseed
                #pragma unroll
                for (int jj = 0; jj < 8; ++jj) {
                    // D path (MUFU): u' = u - lam * 2^(beta * lg2(u))
                    float l  = lg2a(u);
                    float pw = ex2a(beta * l);
                    u = fmaf(nlam, pw, u);
                    // sigmoid: g = 1/(1+e); advance e geometrically
                    float g = rcpa(1.0f + e);
                    e *= c;
                    // F = clip((1 + mu*g)*F + eps*g, 0, 1)
                    float q = fmaf(mu, F, 1e-12f);
                    F = fminf(fmaxf(fmaf(g, q, F), 0.0f), 1.0f);
                    sp[j8 + jj] = fmaf(kf, F, fmaf(nkd, u, kd));
                }
            } else {
                #pragma unroll
                for (int jj = 0; jj < 8; ++jj) {
                    float l  = lg2a(u);
                    float pw = ex2a(beta * l);
                    u = fmaf(nlam, pw, u);
                    float z = fmaf((float)jj, na, zs);   // literal jj: one FFMA
                    float e = ex2a(z);                   // saturates safely
                    float g = rcpa(1.0f + e);
                    float q = fmaf(mu, F, 1e-12f);
                    F = fminf(fmaxf(fmaf(g, q, F), 0.0f), 1.0f);
                    sp[j8 + jj] = fmaf(kf, F, fmaf(nkd, u, kd));
                }
            }
        }
        __syncthreads();
        // coalesced flush: BT lanes x 32 steps, float4 per thread
        #pragma unroll
        for (int it = 0; it < 8; ++it) {
            int q4 = it * (BT * 4) + t * 4;   // word index, lane-major
            int r  = q4 >> 5;                 // lane row within block
            int cc = q4 & 31;                 // step within chunk
            int sb = r * SW + cc;
            float4 v;
            v.x = sm[sb];
            v.y = sm[sb + 1];
            v.z = sm[sb + 2];
            v.w = sm[sb + 3];
            *reinterpret_cast<float4*>(
                &out[(size_t)(base_lane + r) * 200 + n0 + cc]) = v;
        }
        __syncthreads();
    }

    // remainder: 8 steps (n = 192..199), exact path, direct float4 stores
    {
        float* o = out + (size_t)lane * 200 + 192;
        float zc = fmaf(192.0f, na, z0);
        #pragma unroll
        for (int n4 = 0; n4 < 8; n4 += 4) {
            float4 r;
            float* rv = &r.x;
            #pragma unroll
            for (int j = 0; j < 4; ++j) {
                float l  = lg2a(u);
                float pw = ex2a(beta * l);
                u = fmaf(nlam, pw, u);
                float z = fmaf((float)(n4 + j), na, zc);
                float e = ex2a(z);
                float g = rcpa(1.0f + e);
                float q = fmaf(mu, F, 1e-12f);
                F = fminf(fmaxf(fmaf(g, q, F), 0.0f), 1.0f);
                rv[j] = fmaf(kf, F, fmaf(nkd, u, kd));
            }
            *reinterpret_cast<float4*>(o + n4) = r;
        }
    }
}

// generic fallback for unexpected shapes
__global__ void __launch_bounds__(256) ist_generic(
    const float* __restrict__ in, float* __restrict__ out, int n_lanes)
{
    int tid = blockIdx.x * blockDim.x + threadIdx.x;
    if (tid >= n_lanes) return;
    const float* p = in + (size_t)tid * 7;
    float lam  = 0.001f * fmaxf(p[0], 0.0f);
    float beta = fmaf(10.0f, fmaxf(p[1], 0.0f), 1.0f);
    float kd = p[2], mu = p[3], kf = p[4];
    float a = LOG2E_F / p[6], z0 = p[5] * a;
    float u = 1.0f, F = 1e-12f, nf = 0.0f;
    float* o = out + (size_t)tid * 200;
    for (int n = 0; n < 200; ++n) {
        float l  = lg2a(fmaxf(u, 1e-12f));
        float pw = ex2a(beta * l);
        u = fminf(fmaxf(fmaf(-lam, pw, u), 0.0f), 1.0f);
        float z = fmaf(-nf, a, z0);
        float g = rcpa(1.0f + ex2a(z));
        float q = fmaf(mu, F, 1e-12f);
        F = fminf(fmaxf(fmaf(g, q, F), 0.0f), 1.0f);
        o[n] = fmaf(kf, F, fmaf(-kd, u, kd));
        nf += 1.0f;
    }
}

extern "C" void kernel_launch(void* const* d_in, const int* in_sizes, int n_in,
                              void* d_out, int out_size)
{
    const float* in = (const float*)d_in[0];
    float* out = (float*)d_out;
    int n_lanes = in_sizes[0] / 7;
    if (n_lanes % BT == 0) {
        ist_staged_kernel<<<n_lanes / BT, BT>>>(in, out);
    } else {
        ist_generic<<<(n_lanes + 255) / 256, 256>>>(in, out, n_lanes);
    }
}